// round 9
// baseline (speedup 1.0000x reference)
#include <cuda_runtime.h>
#include <cstdint>

#define NH 64
#define NK 64
#define TM 128          // rows per CTA (pass1)
#define P1T 256
#define P2T 256
#define STRD 68         // smem row stride in floats (conflict-free fragments)

// dynamic smem offsets (floats)
#define F_A    0                      // 128 x 68 (reused as Q stage after GEMM)
#define F_B    (F_A + TM * STRD)      // 64 x 68
#define F_Z2   (F_B + NK * STRD)      // 128
#define F_C2   (F_Z2 + TM)            // 64
#define F_COL  (F_C2 + NK)            // 64
#define SMEM_FLOATS (F_COL + NK)
#define SMEM_BYTES  (SMEM_FLOATS * 4) // 53248

__device__ float g_colsum[NK];
__device__ unsigned g_done;

__device__ __forceinline__ uint32_t smem_u32(const void* p) {
    uint32_t a;
    asm("{ .reg .u64 t; cvta.to.shared.u64 t, %1; cvt.u32.u64 %0, t; }"
        : "=r"(a) : "l"(p));
    return a;
}
#define CP_ASYNC16(dst, src) \
    asm volatile("cp.async.cg.shared.global [%0], [%1], 16;" :: "r"(dst), "l"(src))

__device__ __forceinline__ void mma_tf32(float* d, uint32_t a0, uint32_t a1,
                                         uint32_t a2, uint32_t a3,
                                         uint32_t b0, uint32_t b1) {
    asm volatile(
        "mma.sync.aligned.m16n8k8.row.col.f32.tf32.tf32.f32 "
        "{%0,%1,%2,%3}, {%4,%5,%6,%7}, {%8,%9}, {%0,%1,%2,%3};"
        : "+f"(d[0]), "+f"(d[1]), "+f"(d[2]), "+f"(d[3])
        : "r"(a0), "r"(a1), "r"(a2), "r"(a3), "r"(b0), "r"(b1));
}
__device__ __forceinline__ float sqrt_ap(float x) {
    float r; asm("sqrt.approx.f32 %0, %1;" : "=f"(r) : "f"(x)); return r;
}
__device__ __forceinline__ float rcp_ap(float x) {
    float r; asm("rcp.approx.f32 %0, %1;" : "=f"(r) : "f"(x)); return r;
}

// ---------------------------------------------------------------------------
// Pass 1: Q = rownorm(1/(1+sqrt(max(||z||^2+||c||^2-2 z.c, 0)))) via tf32
// mma.sync. 8 warps x (16 rows x 64 cols), TM=128 rows/CTA, 3 CTAs/SM
// (24 warps/SM). Epilogue in place over the fragments (no spills); Q staged
// through smem for fully coalesced global stores.
// ---------------------------------------------------------------------------
__global__ void __launch_bounds__(P1T, 3)
k_pass1(const float* __restrict__ z, const float* __restrict__ c,
        float* __restrict__ Q) {
    extern __shared__ __align__(16) float sm[];
    const uint32_t sb = smem_u32(sm);
    const int t = threadIdx.x;
    const int warp = t >> 5, lane = t & 31;
    const int g = lane >> 2, tig = lane & 3;

    const long long row0 = (long long)blockIdx.x * TM;

    // Stage z tile (128x64) and centroids (64x64) into stride-68 smem rows.
    {
        const char* zg = (const char*)(z + row0 * NH);
#pragma unroll 8
        for (int i = t; i < TM * 16; i += P1T) {
            int r = i >> 4, c4 = i & 15;
            CP_ASYNC16(sb + (F_A + r * STRD + c4 * 4) * 4, zg + (size_t)i * 16);
        }
#pragma unroll 4
        for (int i = t; i < NK * 16; i += P1T) {
            int r = i >> 4, c4 = i & 15;
            CP_ASYNC16(sb + (F_B + r * STRD + c4 * 4) * 4,
                       ((const char*)c) + (size_t)i * 16);
        }
        asm volatile("cp.async.commit_group;" ::: "memory");
    }
    if (t < NK) sm[F_COL + t] = 0.f;
    asm volatile("cp.async.wait_group 0;" ::: "memory");
    __syncthreads();

    // ||z_r||^2 (threads 0..127) and ||c_n||^2 (threads 128..191).
    if (t < TM + NK) {
        const int rr = (t < TM) ? t : (t - TM);
        const int base = (t < TM) ? (F_A + rr * STRD) : (F_B + rr * STRD);
        float s = 0.f;
        const float4* ar = (const float4*)(sm + base);
#pragma unroll
        for (int j = 0; j < 16; ++j) {
            float4 v = ar[j];
            s = fmaf(v.x, v.x, s); s = fmaf(v.y, v.y, s);
            s = fmaf(v.z, v.z, s); s = fmaf(v.w, v.w, s);
        }
        sm[((t < TM) ? F_Z2 : F_C2) + rr] = s;
    }
    __syncthreads();

    // GEMM: warp w owns rows [w*16, w*16+16); 8 N-tiles of 8 cols.
    float d[8][4];
#pragma unroll
    for (int nt = 0; nt < 8; ++nt)
#pragma unroll
        for (int j = 0; j < 4; ++j) d[nt][j] = 0.f;

    const int rowbase = warp * 16;
    const uint32_t* sA = (const uint32_t*)sm + F_A;
    const uint32_t* sB = (const uint32_t*)sm + F_B;

#pragma unroll
    for (int ks = 0; ks < 8; ++ks) {
        const uint32_t* pa = sA + (rowbase + g) * STRD + ks * 8 + tig;
        uint32_t a0 = pa[0];
        uint32_t a1 = pa[8 * STRD];
        uint32_t a2 = pa[4];
        uint32_t a3 = pa[8 * STRD + 4];
#pragma unroll
        for (int nt = 0; nt < 8; ++nt) {
            const uint32_t* pb = sB + (nt * 8 + g) * STRD + ks * 8 + tig;
            mma_tf32(d[nt], a0, a1, a2, a3, pb[0], pb[4]);
        }
    }

    // Epilogue (in place): thread owns rows r0=rowbase+g, r1=r0+8,
    // cols nt*8 + 2*tig + {0,1}. d[nt][0,1]=row r0, d[nt][2,3]=row r1.
    const float z2a = sm[F_Z2 + rowbase + g];
    const float z2b = sm[F_Z2 + rowbase + g + 8];

    float rs0 = 0.f, rs1 = 0.f;
#pragma unroll
    for (int nt = 0; nt < 8; ++nt) {
        float c2a = sm[F_C2 + nt * 8 + 2 * tig];
        float c2b = sm[F_C2 + nt * 8 + 2 * tig + 1];
        float d2;
        d2 = fmaf(-2.f, d[nt][0], z2a + c2a);
        d[nt][0] = rcp_ap(1.f + sqrt_ap(fmaxf(d2, 0.f)));
        d2 = fmaf(-2.f, d[nt][1], z2a + c2b);
        d[nt][1] = rcp_ap(1.f + sqrt_ap(fmaxf(d2, 0.f)));
        d2 = fmaf(-2.f, d[nt][2], z2b + c2a);
        d[nt][2] = rcp_ap(1.f + sqrt_ap(fmaxf(d2, 0.f)));
        d2 = fmaf(-2.f, d[nt][3], z2b + c2b);
        d[nt][3] = rcp_ap(1.f + sqrt_ap(fmaxf(d2, 0.f)));
        rs0 += d[nt][0] + d[nt][1];
        rs1 += d[nt][2] + d[nt][3];
    }
    // Complete row sums across the tig group.
    rs0 += __shfl_xor_sync(0xffffffffu, rs0, 1);
    rs0 += __shfl_xor_sync(0xffffffffu, rs0, 2);
    rs1 += __shfl_xor_sync(0xffffffffu, rs1, 1);
    rs1 += __shfl_xor_sync(0xffffffffu, rs1, 2);
    rs0 = rcp_ap(rs0);
    rs1 = rcp_ap(rs1);

    __syncthreads();   // all warps done reading the A tile -> reuse as stage

    // Normalize; scatter into smem stage; fold colsum partials into d[nt][0..1].
    float* stage = sm + F_A;
#pragma unroll
    for (int nt = 0; nt < 8; ++nt) {
        float a0 = d[nt][0] * rs0, a1 = d[nt][1] * rs0;
        float b0 = d[nt][2] * rs1, b1 = d[nt][3] * rs1;
        float2 va = {a0, a1}, vb = {b0, b1};
        *(float2*)(stage + (rowbase + g) * STRD + nt * 8 + 2 * tig) = va;
        *(float2*)(stage + (rowbase + g + 8) * STRD + nt * 8 + 2 * tig) = vb;
        d[nt][0] = a0 + b0;
        d[nt][1] = a1 + b1;
    }
    // Column sums across the g group (covers all 16 rows of this warp).
#pragma unroll
    for (int nt = 0; nt < 8; ++nt) {
#pragma unroll
        for (int j = 0; j < 2; ++j) {
            d[nt][j] += __shfl_xor_sync(0xffffffffu, d[nt][j], 4);
            d[nt][j] += __shfl_xor_sync(0xffffffffu, d[nt][j], 8);
            d[nt][j] += __shfl_xor_sync(0xffffffffu, d[nt][j], 16);
        }
    }
    if (g == 0) {
#pragma unroll
        for (int nt = 0; nt < 8; ++nt) {
            atomicAdd(&sm[F_COL + nt * 8 + 2 * tig], d[nt][0]);
            atomicAdd(&sm[F_COL + nt * 8 + 2 * tig + 1], d[nt][1]);
        }
    }
    __syncthreads();

    // Fully coalesced Q writeback (float4, consecutive across the CTA).
    float4* out = (float4*)(Q + row0 * NH);
#pragma unroll 8
    for (int i = t; i < TM * 16; i += P1T) {
        int rr = i >> 4, cc = i & 15;
        out[i] = *(const float4*)(stage + rr * STRD + cc * 4);
    }
    if (t < NK) atomicAdd(&g_colsum[t], sm[F_COL + t]);
}

// ---------------------------------------------------------------------------
// Pass 2: P = rownorm(Q^2 / colsum). Quarter-row per thread. Reverse block
// order (neutral-to-positive for L2 reuse). Last block re-zeroes colsum +
// ticket so every graph replay starts clean.
// ---------------------------------------------------------------------------
__global__ void __launch_bounds__(P2T)
k_pass2(const float* __restrict__ Q, float* __restrict__ P) {
    __shared__ float s_ic[NK];
    const int t = threadIdx.x;
    if (t < NK) s_ic[t] = rcp_ap(g_colsum[t]);
    __syncthreads();

    if (t == 0) {
        unsigned old = atomicAdd(&g_done, 1u);
        if (old == gridDim.x - 1) {
#pragma unroll
            for (int k = 0; k < NK; ++k) g_colsum[k] = 0.f;
            g_done = 0;
            __threadfence();
        }
    }

    const int blk = gridDim.x - 1 - blockIdx.x;
    const long long row = (long long)blk * (P2T / 4) + (t >> 2);
    const int qpart = t & 3;
    const float4* __restrict__ qr =
        (const float4*)(Q + row * NH + qpart * 16);
    const float* ic = s_ic + qpart * 16;

    float p[16];
    float rs = 0.f;
#pragma unroll
    for (int j = 0; j < 4; ++j) {
        float4 v = qr[j];
        float p0 = v.x * v.x * ic[4 * j + 0];
        float p1 = v.y * v.y * ic[4 * j + 1];
        float p2 = v.z * v.z * ic[4 * j + 2];
        float p3 = v.w * v.w * ic[4 * j + 3];
        p[4 * j + 0] = p0; p[4 * j + 1] = p1;
        p[4 * j + 2] = p2; p[4 * j + 3] = p3;
        rs += (p0 + p1) + (p2 + p3);
    }
    rs += __shfl_xor_sync(0xffffffffu, rs, 1);
    rs += __shfl_xor_sync(0xffffffffu, rs, 2);
    const float inv = rcp_ap(rs);

    float4* __restrict__ po = (float4*)(P + row * NH + qpart * 16);
#pragma unroll
    for (int j = 0; j < 4; ++j) {
        float4 v;
        v.x = p[4 * j + 0] * inv;
        v.y = p[4 * j + 1] * inv;
        v.z = p[4 * j + 2] * inv;
        v.w = p[4 * j + 3] * inv;
        po[j] = v;
    }
}

// ---------------------------------------------------------------------------
extern "C" void kernel_launch(void* const* d_in, const int* in_sizes, int n_in,
                              void* d_out, int out_size) {
    const float* z = (const float*)d_in[0];  // (BS, 64)
    const float* c = (const float*)d_in[1];  // (64, 64)
    const long long n_rows = (long long)in_sizes[0] / NH;

    float* Q = (float*)d_out;
    float* P = Q + n_rows * NK;

    static bool attr_set = false;
    if (!attr_set) {
        cudaFuncSetAttribute(k_pass1, cudaFuncAttributeMaxDynamicSharedMemorySize,
                             SMEM_BYTES);
        attr_set = true;
    }

    k_pass1<<<(int)(n_rows / TM), P1T, SMEM_BYTES>>>(z, c, Q);
    k_pass2<<<(int)(n_rows / (P2T / 4)), P2T>>>(Q, P);
}

// round 10
// speedup vs baseline: 1.2444x; 1.2444x over previous
#include <cuda_runtime.h>
#include <cuda_fp16.h>
#include <cstdint>

#define NH 64
#define NK 64
#define TM 128          // rows per CTA (pass1)
#define P1T 128
#define P2T 256
#define STRD 68         // fp32 stage row stride (floats)

// word (4B) offsets in dynamic smem
#define WA   0          // A half-tile: 128 rows x 32 words (64 halfs), swizzled
#define WB   4096       // B half-tile: 64 rows x 32 words
#define WSTG 0          // fp32 Q stage (128 x 68) overlaps A/B after GEMM
#define WZ2  8704       // 128 floats
#define WC2  8832       // 64
#define WCOL 8896       // 64
#define SMEM_WORDS 8960
#define SMEM_BYTES (SMEM_WORDS * 4)   // 35840

__device__ float g_colsum[NK];
__device__ unsigned g_done;

__device__ __forceinline__ void mma_f16(float* d, uint32_t a0, uint32_t a1,
                                        uint32_t a2, uint32_t a3,
                                        uint32_t b0, uint32_t b1) {
    asm volatile(
        "mma.sync.aligned.m16n8k16.row.col.f32.f16.f16.f32 "
        "{%0,%1,%2,%3}, {%4,%5,%6,%7}, {%8,%9}, {%0,%1,%2,%3};"
        : "+f"(d[0]), "+f"(d[1]), "+f"(d[2]), "+f"(d[3])
        : "r"(a0), "r"(a1), "r"(a2), "r"(a3), "r"(b0), "r"(b1));
}
__device__ __forceinline__ float sqrt_ap(float x) {
    float r; asm("sqrt.approx.f32 %0, %1;" : "=f"(r) : "f"(x)); return r;
}
__device__ __forceinline__ float rcp_ap(float x) {
    float r; asm("rcp.approx.f32 %0, %1;" : "=f"(r) : "f"(x)); return r;
}
__device__ __forceinline__ uint32_t f2h2(float a, float b) {
    __half2 h = __floats2half2_rn(a, b);
    return *reinterpret_cast<uint32_t*>(&h);
}
// swizzled word offset for half tiles: row r, 16B chunk j (0..7), word w (0..3)
__device__ __forceinline__ uint32_t swz(int r, int j, int w) {
    return r * 32 + ((j ^ (r & 7)) << 2) + w;
}

// ---------------------------------------------------------------------------
// Pass 1: Q = rownorm(1/(1+sqrt(max(||z||^2+||c||^2-2 z.c, 0)))) via fp16
// m16n8k16 mma.sync (same mantissa as tf32, half the MMAs + half the LDS).
// 4 warps x (32 rows x 64 cols), TM=128 rows/CTA.
// ---------------------------------------------------------------------------
__global__ void __launch_bounds__(P1T, 4)
k_pass1(const float* __restrict__ z, const float* __restrict__ c,
        float* __restrict__ Q) {
    extern __shared__ __align__(16) uint32_t smw[];
    float* smf = (float*)smw;
    const int t = threadIdx.x;
    const int warp = t >> 5, lane = t & 31;
    const int g = lane >> 2, tig = lane & 3;

    const long long row0 = (long long)blockIdx.x * TM;

    // --- Stage z (128x64 fp32 -> fp16, swizzled), coalesced LDG.128 ---
    {
        const float4* zg = (const float4*)(z + row0 * NH);
#pragma unroll
        for (int k = 0; k < 16; ++k) {
            int i = t + k * P1T;
            float4 v = zg[i];
            int r = i >> 4, c4 = i & 15;
            uint32_t dst = WA + swz(r, c4 >> 1, 2 * (c4 & 1));
            *(uint2*)(smw + dst) = make_uint2(f2h2(v.x, v.y), f2h2(v.z, v.w));
        }
        const float4* cg = (const float4*)c;
#pragma unroll
        for (int k = 0; k < 8; ++k) {
            int i = t + k * P1T;
            float4 v = cg[i];
            int r = i >> 4, c4 = i & 15;
            uint32_t dst = WB + swz(r, c4 >> 1, 2 * (c4 & 1));
            *(uint2*)(smw + dst) = make_uint2(f2h2(v.x, v.y), f2h2(v.z, v.w));
        }
    }
    if (t < NK) smf[WCOL + t] = 0.f;
    __syncthreads();

    // --- ||z_r||^2 (threads 0..127) and ||c_n||^2 (threads 0..63) from tiles
    {
        float s = 0.f;
#pragma unroll
        for (int j = 0; j < 8; ++j) {
            uint4 q = *(const uint4*)(smw + WA + swz(t, j, 0));
            float2 f;
            f = __half22float2(*(__half2*)&q.x); s = fmaf(f.x,f.x,s); s = fmaf(f.y,f.y,s);
            f = __half22float2(*(__half2*)&q.y); s = fmaf(f.x,f.x,s); s = fmaf(f.y,f.y,s);
            f = __half22float2(*(__half2*)&q.z); s = fmaf(f.x,f.x,s); s = fmaf(f.y,f.y,s);
            f = __half22float2(*(__half2*)&q.w); s = fmaf(f.x,f.x,s); s = fmaf(f.y,f.y,s);
        }
        smf[WZ2 + t] = s;
        if (t < NK) {
            float sc = 0.f;
#pragma unroll
            for (int j = 0; j < 8; ++j) {
                uint4 q = *(const uint4*)(smw + WB + swz(t, j, 0));
                float2 f;
                f = __half22float2(*(__half2*)&q.x); sc = fmaf(f.x,f.x,sc); sc = fmaf(f.y,f.y,sc);
                f = __half22float2(*(__half2*)&q.y); sc = fmaf(f.x,f.x,sc); sc = fmaf(f.y,f.y,sc);
                f = __half22float2(*(__half2*)&q.z); sc = fmaf(f.x,f.x,sc); sc = fmaf(f.y,f.y,sc);
                f = __half22float2(*(__half2*)&q.w); sc = fmaf(f.x,f.x,sc); sc = fmaf(f.y,f.y,sc);
            }
            smf[WC2 + t] = sc;
        }
    }
    __syncthreads();

    // --- GEMM: warp w owns rows [w*32, w*32+32); 2 M-tiles x 8 N-tiles,
    //     4 K-steps of 16. Fragment addressing mirrors the tf32 version with
    //     a2/b1 at addr^4 (swizzled second k-half chunk).
    float d[8][2][4];
#pragma unroll
    for (int nt = 0; nt < 8; ++nt)
#pragma unroll
        for (int mt = 0; mt < 2; ++mt)
#pragma unroll
            for (int j = 0; j < 4; ++j) d[nt][mt][j] = 0.f;

    const int rowbase = warp * 32;

#pragma unroll
    for (int ks = 0; ks < 4; ++ks) {
        const int ch = (2 * ks) ^ g;   // swizzled chunk for this lane's rows
        uint32_t a[2][4];
#pragma unroll
        for (int mt = 0; mt < 2; ++mt) {
            uint32_t base = WA + (rowbase + mt * 16 + g) * 32 + (ch << 2) + tig;
            a[mt][0] = smw[base];
            a[mt][1] = smw[base + 256];        // row + 8
            a[mt][2] = smw[base ^ 4];          // second k-half
            a[mt][3] = smw[(base + 256) ^ 4];
        }
        uint32_t b[8][2];
#pragma unroll
        for (int nt = 0; nt < 8; ++nt) {
            uint32_t bb = WB + (nt * 8 + g) * 32 + (ch << 2) + tig;
            b[nt][0] = smw[bb];
            b[nt][1] = smw[bb ^ 4];
        }
#pragma unroll
        for (int nt = 0; nt < 8; ++nt)
#pragma unroll
            for (int mt = 0; mt < 2; ++mt)
                mma_f16(d[nt][mt], a[mt][0], a[mt][1], a[mt][2], a[mt][3],
                        b[nt][0], b[nt][1]);
    }

    // --- Epilogue (in place). Thread owns rows rowbase + mt*16 + hr*8 + g,
    //     cols nt*8 + 2*tig + {0,1}.
    float z2r[4];
    z2r[0] = smf[WZ2 + rowbase + g];
    z2r[1] = smf[WZ2 + rowbase + g + 8];
    z2r[2] = smf[WZ2 + rowbase + g + 16];
    z2r[3] = smf[WZ2 + rowbase + g + 24];

    float rs[4] = {0.f, 0.f, 0.f, 0.f};
#pragma unroll
    for (int nt = 0; nt < 8; ++nt) {
        float c2a = smf[WC2 + nt * 8 + 2 * tig];
        float c2b = smf[WC2 + nt * 8 + 2 * tig + 1];
#pragma unroll
        for (int mt = 0; mt < 2; ++mt) {
#pragma unroll
            for (int hr = 0; hr < 2; ++hr) {
                int r = mt * 2 + hr;
                float da = fmaf(-2.f, d[nt][mt][hr * 2],     z2r[r] + c2a);
                float db = fmaf(-2.f, d[nt][mt][hr * 2 + 1], z2r[r] + c2b);
                float qa = rcp_ap(1.f + sqrt_ap(fmaxf(da, 0.f)));
                float qb = rcp_ap(1.f + sqrt_ap(fmaxf(db, 0.f)));
                d[nt][mt][hr * 2]     = qa;
                d[nt][mt][hr * 2 + 1] = qb;
                rs[r] += qa + qb;
            }
        }
    }
#pragma unroll
    for (int r = 0; r < 4; ++r) {
        rs[r] += __shfl_xor_sync(0xffffffffu, rs[r], 1);
        rs[r] += __shfl_xor_sync(0xffffffffu, rs[r], 2);
        rs[r] = rcp_ap(rs[r]);
    }

    __syncthreads();   // A/B tiles dead -> reuse smem as fp32 Q stage

    float* stage = smf + WSTG;
#pragma unroll
    for (int nt = 0; nt < 8; ++nt) {
        float csa = 0.f, csb = 0.f;
#pragma unroll
        for (int mt = 0; mt < 2; ++mt) {
#pragma unroll
            for (int hr = 0; hr < 2; ++hr) {
                int r = mt * 2 + hr;
                float qa = d[nt][mt][hr * 2] * rs[r];
                float qb = d[nt][mt][hr * 2 + 1] * rs[r];
                csa += qa;
                csb += qb;
                float2 v = {qa, qb};
                *(float2*)(stage + (rowbase + mt * 16 + hr * 8 + g) * STRD +
                           nt * 8 + 2 * tig) = v;
            }
        }
        d[nt][0][0] = csa;
        d[nt][0][1] = csb;
    }
#pragma unroll
    for (int nt = 0; nt < 8; ++nt) {
#pragma unroll
        for (int j = 0; j < 2; ++j) {
            d[nt][0][j] += __shfl_xor_sync(0xffffffffu, d[nt][0][j], 4);
            d[nt][0][j] += __shfl_xor_sync(0xffffffffu, d[nt][0][j], 8);
            d[nt][0][j] += __shfl_xor_sync(0xffffffffu, d[nt][0][j], 16);
        }
    }
    if (g == 0) {
#pragma unroll
        for (int nt = 0; nt < 8; ++nt) {
            atomicAdd(&smf[WCOL + nt * 8 + 2 * tig], d[nt][0][0]);
            atomicAdd(&smf[WCOL + nt * 8 + 2 * tig + 1], d[nt][0][1]);
        }
    }
    __syncthreads();

    // Fully coalesced Q writeback.
    float4* out = (float4*)(Q + row0 * NH);
#pragma unroll 4
    for (int i = t; i < TM * 16; i += P1T) {
        int rr = i >> 4, cc = i & 15;
        out[i] = *(const float4*)(stage + rr * STRD + cc * 4);
    }
    if (t < NK) atomicAdd(&g_colsum[t], smf[WCOL + t]);
}

// ---------------------------------------------------------------------------
// Pass 2: P = rownorm(Q^2 / colsum). Quarter-row per thread (R5/R8 proven).
// Last block re-zeroes colsum + ticket so every graph replay starts clean.
// ---------------------------------------------------------------------------
__global__ void __launch_bounds__(P2T)
k_pass2(const float* __restrict__ Q, float* __restrict__ P) {
    __shared__ float s_ic[NK];
    const int t = threadIdx.x;
    if (t < NK) s_ic[t] = rcp_ap(g_colsum[t]);
    __syncthreads();

    if (t == 0) {
        unsigned old = atomicAdd(&g_done, 1u);
        if (old == gridDim.x - 1) {
#pragma unroll
            for (int k = 0; k < NK; ++k) g_colsum[k] = 0.f;
            g_done = 0;
            __threadfence();
        }
    }

    const long long row = (long long)blockIdx.x * (P2T / 4) + (t >> 2);
    const int qpart = t & 3;
    const float4* __restrict__ qr =
        (const float4*)(Q + row * NH + qpart * 16);
    const float* ic = s_ic + qpart * 16;

    float p[16];
    float rs = 0.f;
#pragma unroll
    for (int j = 0; j < 4; ++j) {
        float4 v = qr[j];
        float p0 = v.x * v.x * ic[4 * j + 0];
        float p1 = v.y * v.y * ic[4 * j + 1];
        float p2 = v.z * v.z * ic[4 * j + 2];
        float p3 = v.w * v.w * ic[4 * j + 3];
        p[4 * j + 0] = p0; p[4 * j + 1] = p1;
        p[4 * j + 2] = p2; p[4 * j + 3] = p3;
        rs += (p0 + p1) + (p2 + p3);
    }
    rs += __shfl_xor_sync(0xffffffffu, rs, 1);
    rs += __shfl_xor_sync(0xffffffffu, rs, 2);
    const float inv = rcp_ap(rs);

    float4* __restrict__ po = (float4*)(P + row * NH + qpart * 16);
#pragma unroll
    for (int j = 0; j < 4; ++j) {
        float4 v;
        v.x = p[4 * j + 0] * inv;
        v.y = p[4 * j + 1] * inv;
        v.z = p[4 * j + 2] * inv;
        v.w = p[4 * j + 3] * inv;
        po[j] = v;
    }
}

// ---------------------------------------------------------------------------
extern "C" void kernel_launch(void* const* d_in, const int* in_sizes, int n_in,
                              void* d_out, int out_size) {
    const float* z = (const float*)d_in[0];  // (BS, 64)
    const float* c = (const float*)d_in[1];  // (64, 64)
    const long long n_rows = (long long)in_sizes[0] / NH;

    float* Q = (float*)d_out;
    float* P = Q + n_rows * NK;

    static bool attr_set = false;
    if (!attr_set) {
        cudaFuncSetAttribute(k_pass1, cudaFuncAttributeMaxDynamicSharedMemorySize,
                             SMEM_BYTES);
        attr_set = true;
    }

    k_pass1<<<(int)(n_rows / TM), P1T, SMEM_BYTES>>>(z, c, Q);
    k_pass2<<<(int)(n_rows / (P2T / 4)), P2T>>>(Q, P);
}

// round 11
// speedup vs baseline: 1.2758x; 1.0252x over previous
#include <cuda_runtime.h>
#include <cuda_fp16.h>
#include <cstdint>

#define NH 64
#define NK 64
#define TM 128          // rows per CTA (pass1)
#define P1T 128
#define P2T 256
#define STRD 68         // fp32 stage row stride (floats)

// word (4B) offsets in dynamic smem
#define WA   0          // A half-tile: 128 rows x 32 words (64 halfs), swizzled
#define WB   4096       // B half-tile: 64 rows x 32 words
#define WSTG 0          // fp32 Q stage (128 x 68) overlaps A/B after GEMM
#define WZ2  8704       // 128 floats
#define WC2  8832       // 64
#define WCOL 8896       // 64
#define SMEM_WORDS 8960
#define SMEM_BYTES (SMEM_WORDS * 4)   // 35840

__device__ float g_colsum[NK];
__device__ unsigned g_done;

__device__ __forceinline__ void mma_f16(float* d, uint32_t a0, uint32_t a1,
                                        uint32_t a2, uint32_t a3,
                                        uint32_t b0, uint32_t b1) {
    asm volatile(
        "mma.sync.aligned.m16n8k16.row.col.f32.f16.f16.f32 "
        "{%0,%1,%2,%3}, {%4,%5,%6,%7}, {%8,%9}, {%0,%1,%2,%3};"
        : "+f"(d[0]), "+f"(d[1]), "+f"(d[2]), "+f"(d[3])
        : "r"(a0), "r"(a1), "r"(a2), "r"(a3), "r"(b0), "r"(b1));
}
__device__ __forceinline__ float sqrt_ap(float x) {
    float r; asm("sqrt.approx.f32 %0, %1;" : "=f"(r) : "f"(x)); return r;
}
__device__ __forceinline__ float rcp_ap(float x) {
    float r; asm("rcp.approx.f32 %0, %1;" : "=f"(r) : "f"(x)); return r;
}
__device__ __forceinline__ uint32_t f2h2(float a, float b) {
    __half2 h = __floats2half2_rn(a, b);
    return *reinterpret_cast<uint32_t*>(&h);
}
// swizzled word offset for half tiles: row r, 16B chunk j (0..7), word w (0..3)
__device__ __forceinline__ uint32_t swz(int r, int j, int w) {
    return r * 32 + ((j ^ (r & 7)) << 2) + w;
}

// ---------------------------------------------------------------------------
// Pass 1: Q = rownorm(1/(1+sqrt(max(||z||^2+||c||^2-2 z.c, 0)))) via fp16
// m16n8k16 mma.sync. 4 warps x (32 rows x 64 cols), TM=128 rows/CTA,
// 5 CTAs/SM for better phase interleaving across co-resident CTAs.
// ---------------------------------------------------------------------------
__global__ void __launch_bounds__(P1T, 5)
k_pass1(const float* __restrict__ z, const float* __restrict__ c,
        float* __restrict__ Q) {
    extern __shared__ __align__(16) uint32_t smw[];
    float* smf = (float*)smw;
    const int t = threadIdx.x;
    const int warp = t >> 5, lane = t & 31;
    const int g = lane >> 2, tig = lane & 3;

    const long long row0 = (long long)blockIdx.x * TM;

    // --- Stage z (128x64 fp32 -> fp16, swizzled), coalesced LDG.128 ---
    {
        const float4* zg = (const float4*)(z + row0 * NH);
#pragma unroll
        for (int k = 0; k < 16; ++k) {
            int i = t + k * P1T;
            float4 v = zg[i];
            int r = i >> 4, c4 = i & 15;
            uint32_t dst = WA + swz(r, c4 >> 1, 2 * (c4 & 1));
            *(uint2*)(smw + dst) = make_uint2(f2h2(v.x, v.y), f2h2(v.z, v.w));
        }
        const float4* cg = (const float4*)c;
#pragma unroll
        for (int k = 0; k < 8; ++k) {
            int i = t + k * P1T;
            float4 v = cg[i];
            int r = i >> 4, c4 = i & 15;
            uint32_t dst = WB + swz(r, c4 >> 1, 2 * (c4 & 1));
            *(uint2*)(smw + dst) = make_uint2(f2h2(v.x, v.y), f2h2(v.z, v.w));
        }
    }
    if (t < NK) smf[WCOL + t] = 0.f;
    __syncthreads();

    // --- ||z_r||^2 (threads 0..127) and ||c_n||^2 (threads 0..63) from tiles
    {
        float s = 0.f;
#pragma unroll
        for (int j = 0; j < 8; ++j) {
            uint4 q = *(const uint4*)(smw + WA + swz(t, j, 0));
            float2 f;
            f = __half22float2(*(__half2*)&q.x); s = fmaf(f.x,f.x,s); s = fmaf(f.y,f.y,s);
            f = __half22float2(*(__half2*)&q.y); s = fmaf(f.x,f.x,s); s = fmaf(f.y,f.y,s);
            f = __half22float2(*(__half2*)&q.z); s = fmaf(f.x,f.x,s); s = fmaf(f.y,f.y,s);
            f = __half22float2(*(__half2*)&q.w); s = fmaf(f.x,f.x,s); s = fmaf(f.y,f.y,s);
        }
        smf[WZ2 + t] = s;
        if (t < NK) {
            float sc = 0.f;
#pragma unroll
            for (int j = 0; j < 8; ++j) {
                uint4 q = *(const uint4*)(smw + WB + swz(t, j, 0));
                float2 f;
                f = __half22float2(*(__half2*)&q.x); sc = fmaf(f.x,f.x,sc); sc = fmaf(f.y,f.y,sc);
                f = __half22float2(*(__half2*)&q.y); sc = fmaf(f.x,f.x,sc); sc = fmaf(f.y,f.y,sc);
                f = __half22float2(*(__half2*)&q.z); sc = fmaf(f.x,f.x,sc); sc = fmaf(f.y,f.y,sc);
                f = __half22float2(*(__half2*)&q.w); sc = fmaf(f.x,f.x,sc); sc = fmaf(f.y,f.y,sc);
            }
            smf[WC2 + t] = sc;
        }
    }
    __syncthreads();

    // --- GEMM: warp w owns rows [w*32, w*32+32); 2 M-tiles x 8 N-tiles,
    //     4 K-steps of 16.
    float d[8][2][4];
#pragma unroll
    for (int nt = 0; nt < 8; ++nt)
#pragma unroll
        for (int mt = 0; mt < 2; ++mt)
#pragma unroll
            for (int j = 0; j < 4; ++j) d[nt][mt][j] = 0.f;

    const int rowbase = warp * 32;

#pragma unroll
    for (int ks = 0; ks < 4; ++ks) {
        const int ch = (2 * ks) ^ g;   // swizzled chunk for this lane's rows
        uint32_t a[2][4];
#pragma unroll
        for (int mt = 0; mt < 2; ++mt) {
            uint32_t base = WA + (rowbase + mt * 16 + g) * 32 + (ch << 2) + tig;
            a[mt][0] = smw[base];
            a[mt][1] = smw[base + 256];        // row + 8
            a[mt][2] = smw[base ^ 4];          // second k-half
            a[mt][3] = smw[(base + 256) ^ 4];
        }
#pragma unroll
        for (int nt = 0; nt < 8; ++nt) {
            uint32_t bb = WB + (nt * 8 + g) * 32 + (ch << 2) + tig;
            uint32_t b0 = smw[bb];
            uint32_t b1 = smw[bb ^ 4];
#pragma unroll
            for (int mt = 0; mt < 2; ++mt)
                mma_f16(d[nt][mt], a[mt][0], a[mt][1], a[mt][2], a[mt][3],
                        b0, b1);
        }
    }

    // --- Epilogue (in place). Thread owns rows rowbase + mt*16 + hr*8 + g,
    //     cols nt*8 + 2*tig + {0,1}.
    float z2r[4];
    z2r[0] = smf[WZ2 + rowbase + g];
    z2r[1] = smf[WZ2 + rowbase + g + 8];
    z2r[2] = smf[WZ2 + rowbase + g + 16];
    z2r[3] = smf[WZ2 + rowbase + g + 24];

    float rs[4] = {0.f, 0.f, 0.f, 0.f};
#pragma unroll
    for (int nt = 0; nt < 8; ++nt) {
        float c2a = smf[WC2 + nt * 8 + 2 * tig];
        float c2b = smf[WC2 + nt * 8 + 2 * tig + 1];
#pragma unroll
        for (int mt = 0; mt < 2; ++mt) {
#pragma unroll
            for (int hr = 0; hr < 2; ++hr) {
                int r = mt * 2 + hr;
                float da = fmaf(-2.f, d[nt][mt][hr * 2],     z2r[r] + c2a);
                float db = fmaf(-2.f, d[nt][mt][hr * 2 + 1], z2r[r] + c2b);
                float qa = rcp_ap(1.f + sqrt_ap(fmaxf(da, 0.f)));
                float qb = rcp_ap(1.f + sqrt_ap(fmaxf(db, 0.f)));
                d[nt][mt][hr * 2]     = qa;
                d[nt][mt][hr * 2 + 1] = qb;
                rs[r] += qa + qb;
            }
        }
    }
#pragma unroll
    for (int r = 0; r < 4; ++r) {
        rs[r] += __shfl_xor_sync(0xffffffffu, rs[r], 1);
        rs[r] += __shfl_xor_sync(0xffffffffu, rs[r], 2);
        rs[r] = rcp_ap(rs[r]);
    }

    __syncthreads();   // A/B tiles dead -> reuse smem as fp32 Q stage

    float* stage = smf + WSTG;
#pragma unroll
    for (int nt = 0; nt < 8; ++nt) {
        float csa = 0.f, csb = 0.f;
#pragma unroll
        for (int mt = 0; mt < 2; ++mt) {
#pragma unroll
            for (int hr = 0; hr < 2; ++hr) {
                int r = mt * 2 + hr;
                float qa = d[nt][mt][hr * 2] * rs[r];
                float qb = d[nt][mt][hr * 2 + 1] * rs[r];
                csa += qa;
                csb += qb;
                float2 v = {qa, qb};
                *(float2*)(stage + (rowbase + mt * 16 + hr * 8 + g) * STRD +
                           nt * 8 + 2 * tig) = v;
            }
        }
        d[nt][0][0] = csa;
        d[nt][0][1] = csb;
    }
#pragma unroll
    for (int nt = 0; nt < 8; ++nt) {
#pragma unroll
        for (int j = 0; j < 2; ++j) {
            d[nt][0][j] += __shfl_xor_sync(0xffffffffu, d[nt][0][j], 4);
            d[nt][0][j] += __shfl_xor_sync(0xffffffffu, d[nt][0][j], 8);
            d[nt][0][j] += __shfl_xor_sync(0xffffffffu, d[nt][0][j], 16);
        }
    }
    if (g == 0) {
#pragma unroll
        for (int nt = 0; nt < 8; ++nt) {
            atomicAdd(&smf[WCOL + nt * 8 + 2 * tig], d[nt][0][0]);
            atomicAdd(&smf[WCOL + nt * 8 + 2 * tig + 1], d[nt][0][1]);
        }
    }
    __syncthreads();

    // Fully coalesced Q writeback.
    float4* out = (float4*)(Q + row0 * NH);
#pragma unroll 4
    for (int i = t; i < TM * 16; i += P1T) {
        int rr = i >> 4, cc = i & 15;
        out[i] = *(const float4*)(stage + rr * STRD + cc * 4);
    }
    if (t < NK) atomicAdd(&g_colsum[t], smf[WCOL + t]);
}

// ---------------------------------------------------------------------------
// Pass 2: P = rownorm(Q^2 / colsum). Quarter-row per thread (proven config).
// Last block re-zeroes colsum + ticket so every graph replay starts clean.
// ---------------------------------------------------------------------------
__global__ void __launch_bounds__(P2T)
k_pass2(const float* __restrict__ Q, float* __restrict__ P) {
    __shared__ float s_ic[NK];
    const int t = threadIdx.x;
    if (t < NK) s_ic[t] = rcp_ap(g_colsum[t]);
    __syncthreads();

    if (t == 0) {
        unsigned old = atomicAdd(&g_done, 1u);
        if (old == gridDim.x - 1) {
#pragma unroll
            for (int k = 0; k < NK; ++k) g_colsum[k] = 0.f;
            g_done = 0;
            __threadfence();
        }
    }

    const long long row = (long long)blockIdx.x * (P2T / 4) + (t >> 2);
    const int qpart = t & 3;
    const float4* __restrict__ qr =
        (const float4*)(Q + row * NH + qpart * 16);
    const float* ic = s_ic + qpart * 16;

    float p[16];
    float rs = 0.f;
#pragma unroll
    for (int j = 0; j < 4; ++j) {
        float4 v = qr[j];
        float p0 = v.x * v.x * ic[4 * j + 0];
        float p1 = v.y * v.y * ic[4 * j + 1];
        float p2 = v.z * v.z * ic[4 * j + 2];
        float p3 = v.w * v.w * ic[4 * j + 3];
        p[4 * j + 0] = p0; p[4 * j + 1] = p1;
        p[4 * j + 2] = p2; p[4 * j + 3] = p3;
        rs += (p0 + p1) + (p2 + p3);
    }
    rs += __shfl_xor_sync(0xffffffffu, rs, 1);
    rs += __shfl_xor_sync(0xffffffffu, rs, 2);
    const float inv = rcp_ap(rs);

    float4* __restrict__ po = (float4*)(P + row * NH + qpart * 16);
#pragma unroll
    for (int j = 0; j < 4; ++j) {
        float4 v;
        v.x = p[4 * j + 0] * inv;
        v.y = p[4 * j + 1] * inv;
        v.z = p[4 * j + 2] * inv;
        v.w = p[4 * j + 3] * inv;
        po[j] = v;
    }
}

// ---------------------------------------------------------------------------
extern "C" void kernel_launch(void* const* d_in, const int* in_sizes, int n_in,
                              void* d_out, int out_size) {
    const float* z = (const float*)d_in[0];  // (BS, 64)
    const float* c = (const float*)d_in[1];  // (64, 64)
    const long long n_rows = (long long)in_sizes[0] / NH;

    float* Q = (float*)d_out;
    float* P = Q + n_rows * NK;

    static bool attr_set = false;
    if (!attr_set) {
        cudaFuncSetAttribute(k_pass1, cudaFuncAttributeMaxDynamicSharedMemorySize,
                             SMEM_BYTES);
        attr_set = true;
    }

    k_pass1<<<(int)(n_rows / TM), P1T, SMEM_BYTES>>>(z, c, Q);
    k_pass2<<<(int)(n_rows / (P2T / 4)), P2T>>>(Q, P);
}